// round 14
// baseline (speedup 1.0000x reference)
#include <cuda_runtime.h>
#include <cuda_fp16.h>

// out = x[0]; out[c, ix, iy] += img[c, proj_y, proj_x]
// R14: fp16 random phase, single accT/imgT arrays, SPATIAL pipelining.
// Records classed by row predicates:
//   C0: py<512            (needs imgT lower half only)
//   C1: py>=512 && ix<512
//   C2: py>=512 && ix>=512
// Schedule:
//   k1: prep imgT[src rows<512] + zero ALL accT
//   k2: scatter C0 || prep imgT[src rows>=512]
//   k3: scatter C1                  (after k3: all dst rows<512 complete)
//   k4: scatter C2 || finish dst rows<512
//   k5: finish dst rows>=512
// Scatter is atomic-op bound (~133 Kops/us, 8M reds total); the spatial split
// hides prep-half and finish-half under that floor.

#define HW     (1024 * 1024)
#define HALFP  (512 * 1024)

__device__ __half g_imgT[(size_t)HW * 16];
__device__ __half g_accT[(size_t)HW * 16];

__device__ __forceinline__ void red_add_v4_f16x2(__half* ptr, uint4 v) {
    asm volatile("red.global.add.noftz.v4.f16x2 [%0], {%1, %2, %3, %4};"
                 :: "l"(ptr), "r"(v.x), "r"(v.y), "r"(v.z), "r"(v.w)
                 : "memory");
}

// ---- role bodies ------------------------------------------------------------

// img (16 chans, f32, channel-major) -> imgT[p][c] f16, 2 positions/thread.
__device__ __forceinline__ void prep_img(const float* __restrict__ img, int p2) {
    float2 r[16];
#pragma unroll
    for (int c = 0; c < 16; c++)
        r[c] = __ldg((const float2*)(img + (size_t)c * HW + p2));

    __half2 h0[8], h1[8];
#pragma unroll
    for (int j = 0; j < 8; j++) {
        h0[j] = __floats2half2_rn(r[2 * j].x, r[2 * j + 1].x);  // pos p2
        h1[j] = __floats2half2_rn(r[2 * j].y, r[2 * j + 1].y);  // pos p2+1
    }
    uint4* d = (uint4*)(g_imgT + (size_t)p2 * 16);  // 64 B contiguous
    d[0] = ((const uint4*)h0)[0];
    d[1] = ((const uint4*)h0)[1];
    d[2] = ((const uint4*)h1)[0];
    d[3] = ((const uint4*)h1)[1];
}

__device__ __forceinline__ void zero_acc(int p2) {
    uint4* z = (uint4*)(g_accT + (size_t)p2 * 16);
    uint4 zero = make_uint4(0, 0, 0, 0);
    z[0] = zero; z[1] = zero; z[2] = zero; z[3] = zero;
}

__device__ __forceinline__ void gather_add(int src, int dst) {
    const uint4* s = (const uint4*)(g_imgT + (size_t)src * 16);
    uint4 v0 = __ldg(s + 0);
    uint4 v1 = __ldg(s + 1);
    __half* d = g_accT + (size_t)dst * 16;
    red_add_v4_f16x2(d,     v0);
    red_add_v4_f16x2(d + 8, v1);
}

// CLS 0: py<512 | CLS 1: py>=512 && ix<512 | CLS 2: py>=512 && ix>=512
template <int CLS>
__device__ __forceinline__ bool selected(int py, int ix) {
    if (CLS == 0) return py < 512;
    if (CLS == 1) return (py >= 512) & (ix < 512);
    return (py >= 512) & (ix >= 512);
}

template <int CLS>
__device__ __forceinline__ void scatter_block(const int* __restrict__ index_x,
                                              const int* __restrict__ index_y,
                                              const int* __restrict__ proj_x,
                                              const int* __restrict__ proj_y,
                                              int L, int sb, int tid) {
    int l4 = (sb * 256 + tid) * 4;
    if (l4 + 3 < L) {
        int4 ix = __ldg((const int4*)(index_x + l4));
        int4 iy = __ldg((const int4*)(index_y + l4));
        int4 px = __ldg((const int4*)(proj_x + l4));
        int4 py = __ldg((const int4*)(proj_y + l4));

        if (selected<CLS>(py.x, ix.x)) gather_add(py.x * 1024 + px.x, ix.x * 1024 + iy.x);
        if (selected<CLS>(py.y, ix.y)) gather_add(py.y * 1024 + px.y, ix.y * 1024 + iy.y);
        if (selected<CLS>(py.z, ix.z)) gather_add(py.z * 1024 + px.z, ix.z * 1024 + iy.z);
        if (selected<CLS>(py.w, ix.w)) gather_add(py.w * 1024 + px.w, ix.w * 1024 + iy.w);
    } else {
        for (int l = l4; l < L; l++) {
            int pyv = __ldg(proj_y + l), ixv = __ldg(index_x + l);
            if (selected<CLS>(pyv, ixv))
                gather_add(pyv * 1024 + __ldg(proj_x + l),
                           ixv * 1024 + __ldg(index_y + l));
        }
    }
}

// out[c][p] = x[c][p] + f32(accT[p][c]) for p in [base, base+HALFP).
__device__ __forceinline__ void finish_block(const float* __restrict__ x,
                                             float* __restrict__ out,
                                             int base, int fb, int tid) {
    int p2 = base + (fb * 256 + tid) * 2;

    uint4 v[4];
    const uint4* a = (const uint4*)(g_accT + (size_t)p2 * 16);
#pragma unroll
    for (int i = 0; i < 4; i++) v[i] = a[i];
    const __half* h = (const __half*)v;  // h[j*16 + c] = acc[p2+j][c]

#pragma unroll
    for (int c = 0; c < 16; c++) {
        float2 xv = __ldg((const float2*)(x + (size_t)c * HW + p2));
        *(float2*)(out + (size_t)c * HW + p2) =
            make_float2(xv.x + __half2float(h[c]),
                        xv.y + __half2float(h[16 + c]));
    }
}

// ---- kernels --------------------------------------------------------------

#define NZERO  (HW / 2 / 256)      // 2048 blocks cover all positions (zeroing)
#define NHALF  (HALFP / 2 / 256)   // 1024 blocks cover a position half

// k1: zero all accT; prep imgT for positions < HALFP (src rows < 512).
__global__ void __launch_bounds__(256) k1(const float* __restrict__ img) {
    int p2 = (blockIdx.x * 256 + threadIdx.x) * 2;
    zero_acc(p2);
    if (p2 < HALFP) prep_img(img, p2);
}

// k2: scatter C0 (3 of 4 blocks) || prep imgT upper half (1 of 4).
__global__ void __launch_bounds__(256) k2(const float* __restrict__ img,
                                          const int* __restrict__ index_x,
                                          const int* __restrict__ index_y,
                                          const int* __restrict__ proj_x,
                                          const int* __restrict__ proj_y,
                                          int L, int NS) {
    int g = blockIdx.x >> 2, r = blockIdx.x & 3;
    if (r < 3) {
        int sb = g * 3 + r;
        if (sb < NS) scatter_block<0>(index_x, index_y, proj_x, proj_y, L, sb, threadIdx.x);
    } else {
        if (g < NHALF) {
            int p2 = HALFP + (g * 256 + threadIdx.x) * 2;
            prep_img(img, p2);
        }
    }
}

// k3: scatter C1 solo.
__global__ void __launch_bounds__(256) k3(const int* __restrict__ index_x,
                                          const int* __restrict__ index_y,
                                          const int* __restrict__ proj_x,
                                          const int* __restrict__ proj_y,
                                          int L) {
    scatter_block<1>(index_x, index_y, proj_x, proj_y, L, blockIdx.x, threadIdx.x);
}

// k4: scatter C2 (3 of 4 blocks) || finish dst rows<512 (1 of 4).
__global__ void __launch_bounds__(256) k4(const float* __restrict__ x,
                                          float* __restrict__ out,
                                          const int* __restrict__ index_x,
                                          const int* __restrict__ index_y,
                                          const int* __restrict__ proj_x,
                                          const int* __restrict__ proj_y,
                                          int L, int NS) {
    int g = blockIdx.x >> 2, r = blockIdx.x & 3;
    if (r < 3) {
        int sb = g * 3 + r;
        if (sb < NS) scatter_block<2>(index_x, index_y, proj_x, proj_y, L, sb, threadIdx.x);
    } else {
        if (g < NHALF) finish_block(x, out, 0, g, threadIdx.x);
    }
}

// k5: finish dst rows>=512.
__global__ void __launch_bounds__(256) k5(const float* __restrict__ x,
                                          float* __restrict__ out) {
    finish_block(x, out, HALFP, blockIdx.x, threadIdx.x);
}

extern "C" void kernel_launch(void* const* d_in, const int* in_sizes, int n_in,
                              void* d_out, int out_size) {
    const float* x       = (const float*)d_in[0];
    const float* img     = (const float*)d_in[1];
    const int*   index_x = (const int*)d_in[2];
    const int*   index_y = (const int*)d_in[3];
    const int*   proj_x  = (const int*)d_in[4];
    const int*   proj_y  = (const int*)d_in[5];
    float*       out     = (float*)d_out;

    const int L = in_sizes[2];

    int NS = (L / 4 + 255) / 256 + 1;     // scatter blocks (tail-safe)
    int g34 = (NS + 2) / 3;
    int groups = (g34 > NHALF) ? g34 : NHALF;
    int NB = 4 * groups;

    k1<<<NZERO, 256>>>(img);
    k2<<<NB, 256>>>(img, index_x, index_y, proj_x, proj_y, L, NS);
    k3<<<NS, 256>>>(index_x, index_y, proj_x, proj_y, L);
    k4<<<NB, 256>>>(x, out, index_x, index_y, proj_x, proj_y, L, NS);
    k5<<<NHALF, 256>>>(x, out);
}

// round 15
// speedup vs baseline: 1.0370x; 1.0370x over previous
#include <cuda_runtime.h>
#include <cuda_fp16.h>

// out = x[0]; out[c, ix, iy] += img[c, proj_y, proj_x]
// R15: R13 (fp16 random phase, channel-split, x never quantized) plus a
// destination-row split of scatter1 so finish1-lower hides under scatter1b.
//   imgT_h[p][j] = f16(img[8h+j][p]); accT_h starts zero (f16).
//   scatter_h: one red.global.add.noftz.v4.f16x2 (16 B) per record-half.
//   finish_h: out[8h+j][p] = x[8h+j][p] + f32(accT_h[p][j])
// Schedule:
//   A: prep0
//   B: scatter0(all) || prep1          (2:1)
//   C: scatter1a(ix<512) || finish0    (2:1)
//   D: scatter1b(ix>=512) || finish1-lower(dst<512)  (4:1)
//   E: finish1-upper

#define HW    (1024 * 1024)
#define HALFP (512 * 1024)

__device__ __half g_imgT0[(size_t)HW * 8];
__device__ __half g_imgT1[(size_t)HW * 8];
__device__ __half g_accT0[(size_t)HW * 8];
__device__ __half g_accT1[(size_t)HW * 8];

__device__ __forceinline__ void red_add_v4_f16x2(__half* ptr, uint4 v) {
    asm volatile("red.global.add.noftz.v4.f16x2 [%0], {%1, %2, %3, %4};"
                 :: "l"(ptr), "r"(v.x), "r"(v.y), "r"(v.z), "r"(v.w)
                 : "memory");
}

// ---- role bodies ------------------------------------------------------------

// Transpose img chans [8h,8h+8) -> imgT_h (f16), zero accT_h. 2 pos/thread.
template <int HALF>
__device__ __forceinline__ void prep_block(const float* __restrict__ img,
                                           int pb, int tid) {
    __half* __restrict__ imgTh = (HALF == 0) ? g_imgT0 : g_imgT1;
    __half* __restrict__ accTh = (HALF == 0) ? g_accT0 : g_accT1;
    const size_t choff = (size_t)(HALF * 8) * HW;

    int p2 = (pb * 256 + tid) * 2;
    if (p2 >= HW) return;

    float2 r[8];
#pragma unroll
    for (int c = 0; c < 8; c++)
        r[c] = __ldg((const float2*)(img + choff + (size_t)c * HW + p2));

    __half2 h0[4], h1[4];
#pragma unroll
    for (int j = 0; j < 4; j++) {
        h0[j] = __floats2half2_rn(r[2 * j].x, r[2 * j + 1].x);  // pos p2
        h1[j] = __floats2half2_rn(r[2 * j].y, r[2 * j + 1].y);  // pos p2+1
    }
    uint4* d = (uint4*)(imgTh + (size_t)p2 * 8);
    d[0] = *(const uint4*)h0;
    d[1] = *(const uint4*)h1;

    uint4* z = (uint4*)(accTh + (size_t)p2 * 8);
    z[0] = make_uint4(0, 0, 0, 0);
    z[1] = make_uint4(0, 0, 0, 0);
}

// MODE 0: all records | MODE 1: ix<512 | MODE 2: ix>=512
template <int MODE>
__device__ __forceinline__ bool selected(int ix) {
    if (MODE == 0) return true;
    if (MODE == 1) return ix < 512;
    return ix >= 512;
}

template <int HALF, int MODE>
__device__ __forceinline__ void scatter_block(const int* __restrict__ index_x,
                                              const int* __restrict__ index_y,
                                              const int* __restrict__ proj_x,
                                              const int* __restrict__ proj_y,
                                              int L, int sb, int tid) {
    const __half* __restrict__ imgTh = (HALF == 0) ? g_imgT0 : g_imgT1;
    __half* __restrict__ accTh       = (HALF == 0) ? g_accT0 : g_accT1;

    int l4 = (sb * 256 + tid) * 4;
    if (l4 + 3 < L) {
        int4 ix = __ldg((const int4*)(index_x + l4));
        int4 iy = __ldg((const int4*)(index_y + l4));
        int4 px = __ldg((const int4*)(proj_x + l4));
        int4 py = __ldg((const int4*)(proj_y + l4));

        if (selected<MODE>(ix.x)) {
            uint4 v = __ldg((const uint4*)(imgTh + (size_t)(py.x * 1024 + px.x) * 8));
            red_add_v4_f16x2(accTh + (size_t)(ix.x * 1024 + iy.x) * 8, v);
        }
        if (selected<MODE>(ix.y)) {
            uint4 v = __ldg((const uint4*)(imgTh + (size_t)(py.y * 1024 + px.y) * 8));
            red_add_v4_f16x2(accTh + (size_t)(ix.y * 1024 + iy.y) * 8, v);
        }
        if (selected<MODE>(ix.z)) {
            uint4 v = __ldg((const uint4*)(imgTh + (size_t)(py.z * 1024 + px.z) * 8));
            red_add_v4_f16x2(accTh + (size_t)(ix.z * 1024 + iy.z) * 8, v);
        }
        if (selected<MODE>(ix.w)) {
            uint4 v = __ldg((const uint4*)(imgTh + (size_t)(py.w * 1024 + px.w) * 8));
            red_add_v4_f16x2(accTh + (size_t)(ix.w * 1024 + iy.w) * 8, v);
        }
    } else {
        for (int l = l4; l < L; l++) {
            int ixv = __ldg(index_x + l);
            if (selected<MODE>(ixv)) {
                int src = __ldg(proj_y + l) * 1024 + __ldg(proj_x + l);
                int dst = ixv * 1024 + __ldg(index_y + l);
                uint4 v = __ldg((const uint4*)(imgTh + (size_t)src * 8));
                red_add_v4_f16x2(accTh + (size_t)dst * 8, v);
            }
        }
    }
}

// out[8h+j][p] = x[8h+j][p] + f32(accT_h[p][j]) for p2 = base + slot*2.
template <int HALF>
__device__ __forceinline__ void finish_block(const float* __restrict__ x,
                                             float* __restrict__ out,
                                             int base, int fb, int tid) {
    const __half* __restrict__ accTh = (HALF == 0) ? g_accT0 : g_accT1;
    const size_t choff = (size_t)(HALF * 8) * HW;

    int p2 = base + (fb * 256 + tid) * 2;

    uint4 v[2];
    v[0] = *(const uint4*)(accTh + (size_t)p2 * 8);
    v[1] = *(const uint4*)(accTh + (size_t)(p2 + 1) * 8);
    const __half* h = (const __half*)v;  // h[j*8 + c] = acc[p2+j][8h+c]

#pragma unroll
    for (int c = 0; c < 8; c++) {
        float2 xv = __ldg((const float2*)(x + choff + (size_t)c * HW + p2));
        *(float2*)(out + choff + (size_t)c * HW + p2) =
            make_float2(xv.x + __half2float(h[c]),
                        xv.y + __half2float(h[8 + c]));
    }
}

// ---- kernels --------------------------------------------------------------

#define NPREP  (HW / 2 / 256)      // 2048 groups cover all HW positions
#define NHALF  (HALFP / 2 / 256)   // 1024 groups cover one position half

__global__ void __launch_bounds__(256) kA_prep0(const float* __restrict__ img) {
    prep_block<0>(img, blockIdx.x, threadIdx.x);
}

// B: scatter0 all (2 of 3) || prep1 (1 of 3)
__global__ void __launch_bounds__(256) kB(const float* __restrict__ img,
                                          const int* __restrict__ index_x,
                                          const int* __restrict__ index_y,
                                          const int* __restrict__ proj_x,
                                          const int* __restrict__ proj_y,
                                          int L, int NS) {
    int g = blockIdx.x / 3, r = blockIdx.x % 3;
    if (r < 2) {
        int sb = g * 2 + r;
        if (sb < NS) scatter_block<0, 0>(index_x, index_y, proj_x, proj_y, L, sb, threadIdx.x);
    } else {
        if (g < NPREP) prep_block<1>(img, g, threadIdx.x);
    }
}

// C: scatter1a (ix<512) (2 of 3) || finish0 all positions (1 of 3)
__global__ void __launch_bounds__(256) kC(const float* __restrict__ x,
                                          float* __restrict__ out,
                                          const int* __restrict__ index_x,
                                          const int* __restrict__ index_y,
                                          const int* __restrict__ proj_x,
                                          const int* __restrict__ proj_y,
                                          int L, int NS) {
    int g = blockIdx.x / 3, r = blockIdx.x % 3;
    if (r < 2) {
        int sb = g * 2 + r;
        if (sb < NS) scatter_block<1, 1>(index_x, index_y, proj_x, proj_y, L, sb, threadIdx.x);
    } else {
        if (g < NPREP) finish_block<0>(x, out, 0, g, threadIdx.x);
    }
}

// D: scatter1b (ix>=512) (4 of 5) || finish1 lower positions (1 of 5)
__global__ void __launch_bounds__(256) kD(const float* __restrict__ x,
                                          float* __restrict__ out,
                                          const int* __restrict__ index_x,
                                          const int* __restrict__ index_y,
                                          const int* __restrict__ proj_x,
                                          const int* __restrict__ proj_y,
                                          int L, int NS) {
    int g = blockIdx.x / 5, r = blockIdx.x % 5;
    if (r < 4) {
        int sb = g * 4 + r;
        if (sb < NS) scatter_block<1, 2>(index_x, index_y, proj_x, proj_y, L, sb, threadIdx.x);
    } else {
        if (g < NHALF) finish_block<1>(x, out, 0, g, threadIdx.x);
    }
}

// E: finish1 upper positions
__global__ void __launch_bounds__(256) kE(const float* __restrict__ x,
                                          float* __restrict__ out) {
    finish_block<1>(x, out, HALFP, blockIdx.x, threadIdx.x);
}

extern "C" void kernel_launch(void* const* d_in, const int* in_sizes, int n_in,
                              void* d_out, int out_size) {
    const float* x       = (const float*)d_in[0];
    const float* img     = (const float*)d_in[1];
    const int*   index_x = (const int*)d_in[2];
    const int*   index_y = (const int*)d_in[3];
    const int*   proj_x  = (const int*)d_in[4];
    const int*   proj_y  = (const int*)d_in[5];
    float*       out     = (float*)d_out;

    const int L = in_sizes[2];

    int NS = (L / 4 + 255) / 256 + 1;   // scatter blocks (tail-safe)

    int gB = ((NS + 1) / 2 > NPREP) ? (NS + 1) / 2 : NPREP;
    int gC = gB;
    int gD = ((NS + 3) / 4 > NHALF) ? (NS + 3) / 4 : NHALF;

    kA_prep0<<<NPREP, 256>>>(img);
    kB<<<3 * gB, 256>>>(img, index_x, index_y, proj_x, proj_y, L, NS);
    kC<<<3 * gC, 256>>>(x, out, index_x, index_y, proj_x, proj_y, L, NS);
    kD<<<5 * gD, 256>>>(x, out, index_x, index_y, proj_x, proj_y, L, NS);
    kE<<<NHALF, 256>>>(x, out);
}

// round 16
// speedup vs baseline: 1.0958x; 1.0567x over previous
#include <cuda_runtime.h>
#include <cuda_fp16.h>

// out = x[0]; out[c, ix, iy] += img[c, proj_y, proj_x]
// R16: lean single-pass design (minimum memory-op count) + ILP experiment.
//   imgT[p][c] = f16(img[c][p])  (32 MB)   accT[p][c] = 0 (f16, 32 MB)
//   scatter: per record 1/4 idx-int4-load x4 arrays + 2x16B gather + 2x16B red
//            -> 5 mem-ops/record, 8 records/thread, two-quad pipeline
//            (all 8 idx loads in flight before gathers) to test latency-bound
//            hypothesis (issue% was ~3%).
//   finish:  out[c][p] = x[c][p] + f32(accT[p][c])  (x stays f32 -> low error)
// 4 launches/iter; ncu -s 5 -c 1 lands on iteration-2's SCATTER.

#define HW    (1024 * 1024)
#define HALFP (512 * 1024)

__device__ __half g_imgT[(size_t)HW * 16];
__device__ __half g_accT[(size_t)HW * 16];

__device__ __forceinline__ void red_add_v4_f16x2(__half* ptr, uint4 v) {
    asm volatile("red.global.add.noftz.v4.f16x2 [%0], {%1, %2, %3, %4};"
                 :: "l"(ptr), "r"(v.x), "r"(v.y), "r"(v.z), "r"(v.w)
                 : "memory");
}

// ---- prep: img -> imgT (f16), zero accT. 2 positions/thread. ---------------

__global__ void __launch_bounds__(256) k_prep(const float* __restrict__ img) {
    int p2 = (blockIdx.x * 256 + threadIdx.x) * 2;
    if (p2 >= HW) return;

    float2 r[16];
#pragma unroll
    for (int c = 0; c < 16; c++)
        r[c] = __ldg((const float2*)(img + (size_t)c * HW + p2));

    __half2 h0[8], h1[8];
#pragma unroll
    for (int j = 0; j < 8; j++) {
        h0[j] = __floats2half2_rn(r[2 * j].x, r[2 * j + 1].x);  // pos p2
        h1[j] = __floats2half2_rn(r[2 * j].y, r[2 * j + 1].y);  // pos p2+1
    }
    uint4* d = (uint4*)(g_imgT + (size_t)p2 * 16);  // 64 B contiguous
    d[0] = ((const uint4*)h0)[0];
    d[1] = ((const uint4*)h0)[1];
    d[2] = ((const uint4*)h1)[0];
    d[3] = ((const uint4*)h1)[1];

    uint4* z = (uint4*)(g_accT + (size_t)p2 * 16);
    uint4 zero = make_uint4(0, 0, 0, 0);
    z[0] = zero; z[1] = zero; z[2] = zero; z[3] = zero;
}

// ---- scatter: single pass, 8 records/thread, two-quad pipeline -------------

__device__ __forceinline__ void quad_gather_red(int4 ix, int4 iy, int4 px, int4 py) {
    int s0 = py.x * 1024 + px.x, d0 = ix.x * 1024 + iy.x;
    int s1 = py.y * 1024 + px.y, d1 = ix.y * 1024 + iy.y;
    int s2 = py.z * 1024 + px.z, d2 = ix.z * 1024 + iy.z;
    int s3 = py.w * 1024 + px.w, d3 = ix.w * 1024 + iy.w;

    const uint4* g0 = (const uint4*)(g_imgT + (size_t)s0 * 16);
    const uint4* g1 = (const uint4*)(g_imgT + (size_t)s1 * 16);
    const uint4* g2 = (const uint4*)(g_imgT + (size_t)s2 * 16);
    const uint4* g3 = (const uint4*)(g_imgT + (size_t)s3 * 16);
    uint4 a0 = __ldg(g0 + 0), a1 = __ldg(g0 + 1);
    uint4 b0 = __ldg(g1 + 0), b1 = __ldg(g1 + 1);
    uint4 c0 = __ldg(g2 + 0), c1 = __ldg(g2 + 1);
    uint4 e0 = __ldg(g3 + 0), e1 = __ldg(g3 + 1);

    __half* w0 = g_accT + (size_t)d0 * 16;
    __half* w1 = g_accT + (size_t)d1 * 16;
    __half* w2 = g_accT + (size_t)d2 * 16;
    __half* w3 = g_accT + (size_t)d3 * 16;
    red_add_v4_f16x2(w0,     a0); red_add_v4_f16x2(w0 + 8, a1);
    red_add_v4_f16x2(w1,     b0); red_add_v4_f16x2(w1 + 8, b1);
    red_add_v4_f16x2(w2,     c0); red_add_v4_f16x2(w2 + 8, c1);
    red_add_v4_f16x2(w3,     e0); red_add_v4_f16x2(w3 + 8, e1);
}

__global__ void __launch_bounds__(256) k_scatter(const int* __restrict__ index_x,
                                                 const int* __restrict__ index_y,
                                                 const int* __restrict__ proj_x,
                                                 const int* __restrict__ proj_y,
                                                 int L) {
    int l8 = (blockIdx.x * 256 + threadIdx.x) * 8;
    if (l8 + 7 < L) {
        // Issue ALL 8 index loads before any gather (hide index latency).
        int4 ixA = __ldg((const int4*)(index_x + l8));
        int4 iyA = __ldg((const int4*)(index_y + l8));
        int4 pxA = __ldg((const int4*)(proj_x + l8));
        int4 pyA = __ldg((const int4*)(proj_y + l8));
        int4 ixB = __ldg((const int4*)(index_x + l8 + 4));
        int4 iyB = __ldg((const int4*)(index_y + l8 + 4));
        int4 pxB = __ldg((const int4*)(proj_x + l8 + 4));
        int4 pyB = __ldg((const int4*)(proj_y + l8 + 4));

        quad_gather_red(ixA, iyA, pxA, pyA);
        quad_gather_red(ixB, iyB, pxB, pyB);
    } else {
        for (int l = l8; l < L; l++) {
            int src = __ldg(proj_y + l) * 1024 + __ldg(proj_x + l);
            int dst = __ldg(index_x + l) * 1024 + __ldg(index_y + l);
            const uint4* s = (const uint4*)(g_imgT + (size_t)src * 16);
            uint4 v0 = __ldg(s + 0);
            uint4 v1 = __ldg(s + 1);
            __half* d = g_accT + (size_t)dst * 16;
            red_add_v4_f16x2(d,     v0);
            red_add_v4_f16x2(d + 8, v1);
        }
    }
}

// ---- finish: out[c][p] = x[c][p] + f32(accT[p][c]), 2 positions/thread -----

__device__ __forceinline__ void finish_body(const float* __restrict__ x,
                                            float* __restrict__ out,
                                            int p2) {
    uint4 v[4];
    const uint4* a = (const uint4*)(g_accT + (size_t)p2 * 16);
#pragma unroll
    for (int i = 0; i < 4; i++) v[i] = a[i];
    const __half* h = (const __half*)v;  // h[j*16 + c] = acc[p2+j][c]

#pragma unroll
    for (int c = 0; c < 16; c++) {
        float2 xv = __ldg((const float2*)(x + (size_t)c * HW + p2));
        *(float2*)(out + (size_t)c * HW + p2) =
            make_float2(xv.x + __half2float(h[c]),
                        xv.y + __half2float(h[16 + c]));
    }
}

__global__ void __launch_bounds__(256) k_fin_lo(const float* __restrict__ x,
                                                float* __restrict__ out) {
    int p2 = (blockIdx.x * 256 + threadIdx.x) * 2;
    finish_body(x, out, p2);
}

__global__ void __launch_bounds__(256) k_fin_hi(const float* __restrict__ x,
                                                float* __restrict__ out) {
    int p2 = HALFP + (blockIdx.x * 256 + threadIdx.x) * 2;
    finish_body(x, out, p2);
}

extern "C" void kernel_launch(void* const* d_in, const int* in_sizes, int n_in,
                              void* d_out, int out_size) {
    const float* x       = (const float*)d_in[0];
    const float* img     = (const float*)d_in[1];
    const int*   index_x = (const int*)d_in[2];
    const int*   index_y = (const int*)d_in[3];
    const int*   proj_x  = (const int*)d_in[4];
    const int*   proj_y  = (const int*)d_in[5];
    float*       out     = (float*)d_out;

    const int L = in_sizes[2];

    int NP = HW / 2 / 256;               // 2048
    int NS = (L / 8 + 255) / 256 + 1;    // 8 records/thread, tail-safe
    int NF = HALFP / 2 / 256;            // 1024 per half

    k_prep<<<NP, 256>>>(img);
    k_scatter<<<NS, 256>>>(index_x, index_y, proj_x, proj_y, L);
    k_fin_lo<<<NF, 256>>>(x, out);
    k_fin_hi<<<NF, 256>>>(x, out);
}